// round 13
// baseline (speedup 1.0000x reference)
#include <cuda_runtime.h>

// Output = sigmoid(2.0) everywhere (reference's s = exp(y-y) == 1; the
// transposed conv is dead code). 64 MiB fp32 constant fill at the
// path-independent LTS write cap (~5.6 TB/s across STG.128/STG.256/
// bulk-async/hybrid; 5 repeat runs, 11.71-12.13us band).
//
// Last knob: wave geometry. regs=16 @ 256thr -> 8 CTAs/SM -> 148*8 = 1184
// resident CTAs. Previous grid=2048 is a ragged 1.73-wave launch. This is a
// persistent single-wave grid (1184 blocks), grid-stride over float4s:
// zero block-churn, uniform finish edge.
// (Resubmission of R11 kernel — R12 bench was an infra failure, no signal.)

static constexpr int THREADS = 256;
static constexpr int BLOCKS  = 1184;   // 148 SMs x 8 CTAs/SM, exactly one wave

__global__ void __launch_bounds__(THREADS) fill_sigmoid2_persist(float4* __restrict__ out4,
                                                                 unsigned n4) {
    const float v = 0.8807970779778823f; // sigmoid(2.0)
    const float4 val = make_float4(v, v, v, v);
    const unsigned stride = BLOCKS * THREADS;              // 303,104 float4s
    unsigned i = blockIdx.x * THREADS + threadIdx.x;
    // 4,194,304 / 303,104 = 13.84 -> threads do 13 or 14 coalesced STG.128s.
    // Unroll 2 to keep >=2 stores in flight past the loop-compare.
    for (; i + stride < n4; i += 2 * stride) {
        out4[i] = val;
        out4[i + stride] = val;
    }
    if (i < n4) out4[i] = val;
}

__global__ void fill_sigmoid2_tail(float* __restrict__ out, int start, int n) {
    int i = start + blockIdx.x * blockDim.x + threadIdx.x;
    if (i < n) out[i] = 0.8807970779778823f;
}

extern "C" void kernel_launch(void* const* d_in, const int* in_sizes, int n_in,
                              void* d_out, int out_size) {
    (void)d_in; (void)in_sizes; (void)n_in;
    float* out = (float*)d_out;

    unsigned n4 = (unsigned)(out_size / 4);                // 4,194,304
    fill_sigmoid2_persist<<<BLOCKS, THREADS>>>((float4*)out, n4);

    int rem = out_size - (int)(n4 * 4);                    // 0 for this shape
    if (rem > 0) {
        int t = 256;
        int b = (rem + t - 1) / t;
        fill_sigmoid2_tail<<<b, t>>>(out, (int)(n4 * 4), out_size);
    }
}

// round 14
// speedup vs baseline: 1.0022x; 1.0022x over previous
#include <cuda_runtime.h>

// FINAL: Output is the constant sigmoid(2.0) everywhere (s = exp(y-y) == 1,
// so the entire transposed conv is dead code). 64 MiB fp32 constant fill.
//
// Closed experiment matrix (kernel dur):
//   STG.128 x8/thr 2048blk  11.71-12.13us  <- this kernel, at the wall
//   STG.256 x4/thr          11.90us        (tied, noise)
//   STG.128 x1/thr 16384blk 12.26us        (issue-limited)
//   persistent 1-wave loop  12.64us        (loop overhead > churn savings)
//   hybrid STG+bulk         13.57us        (no path superposition)
//   bulk-async only         13.89us        (prologue + serialization)
// All converge on a path-independent LTS write cap ~5.6-5.7 TB/s.
// 67.1 MB / 5.7 TB/s = 11.7us floor = measured. Nothing left to optimize.

#ifndef VEC_PER_THREAD
#define VEC_PER_THREAD 8   // 8 x float4 = 128 B per thread
#endif

__global__ void __launch_bounds__(256) fill_sigmoid2_v8(float4* __restrict__ out4) {
    const float v = 0.8807970779778823f; // sigmoid(2.0)
    const float4 val = make_float4(v, v, v, v);
    // Block covers 256*8 = 2048 consecutive float4s (32 KB), strided so each
    // STG.128 is a contiguous 4KB warp transaction. Max index = 4,194,304
    // float4s -> fits in 32-bit; ptxas keeps address math to 1 IMAD/store.
    unsigned base = blockIdx.x * (256u * VEC_PER_THREAD) + threadIdx.x;
#pragma unroll
    for (int k = 0; k < VEC_PER_THREAD; k++) {
        out4[base + (unsigned)k * 256u] = val;
    }
}

__global__ void fill_sigmoid2_tail(float* __restrict__ out, int start, int n) {
    int i = start + blockIdx.x * blockDim.x + threadIdx.x;
    if (i < n) out[i] = 0.8807970779778823f;
}

extern "C" void kernel_launch(void* const* d_in, const int* in_sizes, int n_in,
                              void* d_out, int out_size) {
    (void)d_in; (void)in_sizes; (void)n_in;
    float* out = (float*)d_out;

    const int threads = 256;
    const int f4_per_block = threads * VEC_PER_THREAD;        // 2048 float4 = 32 KB
    int n4 = out_size / 4;                                    // 4,194,304
    int blocks = n4 / f4_per_block;                           // 2048 exact
    int covered4 = blocks * f4_per_block;

    if (blocks > 0) {
        fill_sigmoid2_v8<<<blocks, threads>>>((float4*)out);
    }
    // Remainder (0 for this shape, kept for generality)
    int rem_elems = out_size - covered4 * 4;
    if (rem_elems > 0) {
        int t = 256;
        int b = (rem_elems + t - 1) / t;
        fill_sigmoid2_tail<<<b, t>>>(out, covered4 * 4, out_size);
    }
}